// round 2
// baseline (speedup 1.0000x reference)
#include <cuda_runtime.h>
#include <cstdint>
#include <cstddef>

// Problem constants (fixed by the dataset)
#define NN   8192      // NP == NQ
#define CAP  128       // ELL capacity per row (deg ~ Binom(8192, 32/8192); P(>128) ~ 1e-30)
#define TW   768       // concatenated linear output width (3 x 256)

// -------- scratch (no allocations allowed) --------
// layout: Tp [NN*768] | Tq [NN*768] | hp1 [NN*256] | hq1 [NN*256]
__device__ float g_scratch[2 * NN * TW + 2 * NN * 256];
// layout: idx[4][NN*CAP] | cnt[4][NN]
__device__ int   g_ell[4 * NN * CAP + 4 * NN];

// ============================================================================
// Kernel 1: dense adjacency -> ELL index lists. One warp per row; each lane
// reads float4 (512B per warp-iteration, 64 iterations per 8192-wide row).
// Compaction is per-vector-component ballot: deterministic order (grouped by
// component within each 128-col chunk); sums are order-independent.
// ============================================================================
__global__ __launch_bounds__(256) void build_ell(
    const float* __restrict__ A0, const float* __restrict__ A1,
    const float* __restrict__ A2, const float* __restrict__ A3,
    int* __restrict__ ell)
{
    const int mat = blockIdx.y;
    const float* A = (mat == 0) ? A0 : (mat == 1) ? A1 : (mat == 2) ? A2 : A3;
    const int row  = blockIdx.x * 8 + (threadIdx.x >> 5);
    const int lane = threadIdx.x & 31;
    if (row >= NN) return;

    const float4* ar = (const float4*)(A + (size_t)row * NN);
    int* idx  = ell + (size_t)mat * NN * CAP + (size_t)row * CAP;
    int* cntp = ell + (size_t)4 * NN * CAP + mat * NN + row;

    int cnt = 0;
    for (int base = 0; base < NN / 4; base += 32) {
        float4 v = ar[base + lane];
        const int col0 = (base + lane) * 4;
        float e[4] = {v.x, v.y, v.z, v.w};
#pragma unroll
        for (int c = 0; c < 4; c++) {
            unsigned m = __ballot_sync(0xffffffffu, e[c] != 0.0f);
            if (e[c] != 0.0f) {
                int pos = cnt + __popc(m & ((1u << lane) - 1u));
                if (pos < CAP) idx[pos] = col0 + c;
            }
            cnt += __popc(m);
        }
    }
    if (lane == 0) *cntp = (cnt < CAP) ? cnt : CAP;
}

// ============================================================================
// Kernel 2: fused triple linear  Y[NN,768] = X[NN,K] @ [W0;W1;W2]^T + [B0;B1;B2]
// Each Wk is [256, K] row-major. 128x128 block tile, 8x8 per thread, BK=8,
// double-buffered shared memory with register prefetch.
// ============================================================================
template <int K>
__global__ __launch_bounds__(256) void gemm3(
    const float* __restrict__ X,
    const float* __restrict__ W0, const float* __restrict__ W1, const float* __restrict__ W2,
    const float* __restrict__ B0, const float* __restrict__ B1, const float* __restrict__ B2,
    float* __restrict__ Y)
{
    __shared__ float As[2][8][128];
    __shared__ float Bs[2][8][128];

    const int m0   = blockIdx.x * 128;
    const int cb   = blockIdx.y;         // 0..5 -> 128-wide column block of 768
    const int wsel = cb >> 1;
    const float* W  = (wsel == 0) ? W0 : (wsel == 1) ? W1 : W2;
    const float* Bv = (wsel == 0) ? B0 : (wsel == 1) ? B1 : B2;
    const int nW = (cb & 1) * 128;       // row offset inside the selected W [256,K]

    const int tid = threadIdx.x;
    const int ty = tid >> 4, tx = tid & 15;
    const int lr = tid >> 1;             // 0..127
    const int lc = (tid & 1) * 4;        // 0 or 4

    const float* Ap = X + (size_t)(m0 + lr) * K + lc;
    const float* Bp = W + (size_t)(nW + lr) * K + lc;

    float acc[8][8];
#pragma unroll
    for (int i = 0; i < 8; i++)
#pragma unroll
        for (int j = 0; j < 8; j++) acc[i][j] = 0.f;

    constexpr int NT = K / 8;            // number of K-tiles

    // preload tile 0
    float4 av = *(const float4*)(Ap);
    float4 bv = *(const float4*)(Bp);
    As[0][lc + 0][lr] = av.x; As[0][lc + 1][lr] = av.y;
    As[0][lc + 2][lr] = av.z; As[0][lc + 3][lr] = av.w;
    Bs[0][lc + 0][lr] = bv.x; Bs[0][lc + 1][lr] = bv.y;
    Bs[0][lc + 2][lr] = bv.z; Bs[0][lc + 3][lr] = bv.w;
    __syncthreads();

#pragma unroll 1
    for (int t = 0; t < NT; t++) {
        const int cur = t & 1;
        if (t + 1 < NT) {
            av = *(const float4*)(Ap + (t + 1) * 8);
            bv = *(const float4*)(Bp + (t + 1) * 8);
        }
#pragma unroll
        for (int k = 0; k < 8; k++) {
            float4 a0 = *(const float4*)&As[cur][k][ty * 4];
            float4 a1 = *(const float4*)&As[cur][k][64 + ty * 4];
            float4 b0 = *(const float4*)&Bs[cur][k][tx * 4];
            float4 b1 = *(const float4*)&Bs[cur][k][64 + tx * 4];
            float a[8] = {a0.x, a0.y, a0.z, a0.w, a1.x, a1.y, a1.z, a1.w};
            float b[8] = {b0.x, b0.y, b0.z, b0.w, b1.x, b1.y, b1.z, b1.w};
#pragma unroll
            for (int i = 0; i < 8; i++)
#pragma unroll
                for (int j = 0; j < 8; j++)
                    acc[i][j] = fmaf(a[i], b[j], acc[i][j]);
        }
        if (t + 1 < NT) {
            const int nxt = cur ^ 1;
            As[nxt][lc + 0][lr] = av.x; As[nxt][lc + 1][lr] = av.y;
            As[nxt][lc + 2][lr] = av.z; As[nxt][lc + 3][lr] = av.w;
            Bs[nxt][lc + 0][lr] = bv.x; Bs[nxt][lc + 1][lr] = bv.y;
            Bs[nxt][lc + 2][lr] = bv.z; Bs[nxt][lc + 3][lr] = bv.w;
            __syncthreads();
        }
    }

    float bb[8];
#pragma unroll
    for (int jh = 0; jh < 2; jh++)
#pragma unroll
        for (int j = 0; j < 4; j++)
            bb[jh * 4 + j] = Bv[nW + jh * 64 + tx * 4 + j];

#pragma unroll
    for (int ih = 0; ih < 2; ih++)
#pragma unroll
        for (int i = 0; i < 4; i++) {
            const int r = m0 + ih * 64 + ty * 4 + i;
#pragma unroll
            for (int jh = 0; jh < 2; jh++) {
                const int c = cb * 128 + jh * 64 + tx * 4;
                float4 v;
                v.x = acc[ih * 4 + i][jh * 4 + 0] + bb[jh * 4 + 0];
                v.y = acc[ih * 4 + i][jh * 4 + 1] + bb[jh * 4 + 1];
                v.z = acc[ih * 4 + i][jh * 4 + 2] + bb[jh * 4 + 2];
                v.w = acc[ih * 4 + i][jh * 4 + 3] + bb[jh * 4 + 3];
                *(float4*)&Y[(size_t)r * TW + c] = v;
            }
        }
}

// ============================================================================
// Kernel 3: combine = self + SpMM(idx1, Tother[:,256:512]) + SpMM(idx2, Tother[:,512:768]),
// leaky_relu(0.1), optional row-L2 normalization. One block (256 thr) per row.
// Tother (25 MB) is fully L2-resident -> gathers hit L2.
// ============================================================================
__global__ __launch_bounds__(256) void combine(
    const float* __restrict__ Tself, const float* __restrict__ Tother,
    const int* __restrict__ idx1, const int* __restrict__ cnt1,
    const int* __restrict__ idx2, const int* __restrict__ cnt2,
    float* __restrict__ outp, int do_norm)
{
    __shared__ int   sidx[2 * CAP];
    __shared__ float sred[256];
    const int row = blockIdx.x;
    const int t = threadIdx.x;

    if (t < CAP) sidx[t] = idx1[(size_t)row * CAP + t];
    else         sidx[t] = idx2[(size_t)row * CAP + (t - CAP)];
    const int c1 = cnt1[row];
    const int c2 = cnt2[row];
    __syncthreads();

    float acc = Tself[(size_t)row * TW + t];
    float a0 = 0.f, a1 = 0.f, a2 = 0.f, a3 = 0.f;
    int j = 0;
    for (; j + 4 <= c1; j += 4) {
        a0 += Tother[(size_t)sidx[j + 0] * TW + 256 + t];
        a1 += Tother[(size_t)sidx[j + 1] * TW + 256 + t];
        a2 += Tother[(size_t)sidx[j + 2] * TW + 256 + t];
        a3 += Tother[(size_t)sidx[j + 3] * TW + 256 + t];
    }
    for (; j < c1; j++) a0 += Tother[(size_t)sidx[j] * TW + 256 + t];
    for (j = 0; j + 4 <= c2; j += 4) {
        a0 += Tother[(size_t)sidx[CAP + j + 0] * TW + 512 + t];
        a1 += Tother[(size_t)sidx[CAP + j + 1] * TW + 512 + t];
        a2 += Tother[(size_t)sidx[CAP + j + 2] * TW + 512 + t];
        a3 += Tother[(size_t)sidx[CAP + j + 3] * TW + 512 + t];
    }
    for (; j < c2; j++) a0 += Tother[(size_t)sidx[CAP + j] * TW + 512 + t];

    acc += (a0 + a1) + (a2 + a3);
    acc = (acc > 0.f) ? acc : 0.1f * acc;   // leaky_relu(0.1)

    if (!do_norm) {
        outp[(size_t)row * 256 + t] = acc;
    } else {
        sred[t] = acc * acc;
        __syncthreads();
#pragma unroll
        for (int s = 128; s > 0; s >>= 1) {
            if (t < s) sred[t] += sred[t + s];
            __syncthreads();
        }
        outp[(size_t)row * 256 + t] = acc / (sqrtf(sred[0]) + 1e-9f);
    }
}

// ============================================================================
// Host orchestration (graph-capturable: kernel launches only)
// ============================================================================
extern "C" void kernel_launch(void* const* d_in, const int* in_sizes, int n_in,
                              void* d_out, int out_size)
{
    const float* hp      = (const float*)d_in[0];
    const float* hq      = (const float*)d_in[1];
    const float* a_cons  = (const float*)d_in[2];
    const float* a_prod  = (const float*)d_in[3];
    const float* a_rcons = (const float*)d_in[4];
    const float* a_rprod = (const float*)d_in[5];
    // w/b order: 0 wp1, 1 wq1, 2 wcons1, 3 wrprod1, 4 wprod1, 5 wrcons1,
    //            6 wp2, 7 wq2, 8 wcons2, 9 wrprod2, 10 wprod2, 11 wrcons2
    const float* w[12];
    const float* b[12];
    for (int i = 0; i < 12; i++) {
        w[i] = (const float*)d_in[6 + 2 * i];
        b[i] = (const float*)d_in[7 + 2 * i];
    }
    float* out = (float*)d_out;

    float* scratch = nullptr;
    int*   ell     = nullptr;
    cudaGetSymbolAddress((void**)&scratch, g_scratch);
    cudaGetSymbolAddress((void**)&ell, g_ell);

    float* Tp  = scratch;
    float* Tq  = scratch + (size_t)NN * TW;
    float* hp1 = scratch + (size_t)2 * NN * TW;
    float* hq1 = hp1 + (size_t)NN * 256;

    int* idx[4];
    int* cnt[4];
    for (int m = 0; m < 4; m++) {
        idx[m] = ell + (size_t)m * NN * CAP;
        cnt[m] = ell + (size_t)4 * NN * CAP + (size_t)m * NN;
    }
    // mats: 0 = a_cons [P,Q], 1 = a_prod [Q,P], 2 = a_rev_cons [Q,P], 3 = a_rev_prod [P,Q]
    build_ell<<<dim3(NN / 8, 4), 256>>>(a_cons, a_prod, a_rcons, a_rprod, ell);

    // ---- layer 1 ----
    // Tp = hp @ [wp1; wprod1; wrcons1]^T + b   (cols 0:256 self-P, 256:512 prod, 512:768 rcons)
    gemm3<512><<<dim3(64, 6), 256>>>(hp, w[0], w[4], w[5], b[0], b[4], b[5], Tp);
    // Tq = hq @ [wq1; wcons1; wrprod1]^T + b   (cols 0:256 self-Q, 256:512 cons, 512:768 rprod)
    gemm3<512><<<dim3(64, 6), 256>>>(hq, w[1], w[2], w[3], b[1], b[2], b[3], Tq);
    // hp1 = act(Tp_self + a_cons @ Tq[:,256:512] + a_rev_prod @ Tq[:,512:768])
    combine<<<NN, 256>>>(Tp, Tq, idx[0], cnt[0], idx[3], cnt[3], hp1, 0);
    // hq1 = act(Tq_self + a_prod @ Tp[:,256:512] + a_rev_cons @ Tp[:,512:768])
    combine<<<NN, 256>>>(Tq, Tp, idx[1], cnt[1], idx[2], cnt[2], hq1, 0);

    // ---- layer 2 ----
    gemm3<256><<<dim3(64, 6), 256>>>(hp1, w[6], w[10], w[11], b[6], b[10], b[11], Tp);
    gemm3<256><<<dim3(64, 6), 256>>>(hq1, w[7], w[8],  w[9],  b[7], b[8],  b[9],  Tq);
    combine<<<NN, 256>>>(Tp, Tq, idx[0], cnt[0], idx[3], cnt[3], out, 1);
    combine<<<NN, 256>>>(Tq, Tp, idx[1], cnt[1], idx[2], cnt[2], out + (size_t)NN * 256, 1);
}

// round 6
// speedup vs baseline: 1.0756x; 1.0756x over previous
#include <cuda_runtime.h>
#include <cstdint>
#include <cstddef>

// Problem constants (fixed by the dataset)
#define NN   8192      // NP == NQ
#define CAP  128       // ELL capacity per row (deg ~ Binom(8192, 32/8192); P(>128) ~ 1e-30)
#define TW   768       // concatenated linear output width (3 x 256)

// -------- scratch (no allocations allowed) --------
__device__ float g_scratch[2 * NN * TW + 2 * NN * 256];
__device__ int   g_ell[4 * NN * CAP + 4 * NN];

// ============================================================================
// Kernel 1: dense adjacency -> ELL index lists (warp/row, float4 scan)
// ============================================================================
__global__ __launch_bounds__(256) void build_ell(
    const float* __restrict__ A0, const float* __restrict__ A1,
    const float* __restrict__ A2, const float* __restrict__ A3,
    int* __restrict__ ell)
{
    const int mat = blockIdx.y;
    const float* A = (mat == 0) ? A0 : (mat == 1) ? A1 : (mat == 2) ? A2 : A3;
    const int row  = blockIdx.x * 8 + (threadIdx.x >> 5);
    const int lane = threadIdx.x & 31;
    if (row >= NN) return;

    const float4* ar = (const float4*)(A + (size_t)row * NN);
    int* idx  = ell + (size_t)mat * NN * CAP + (size_t)row * CAP;
    int* cntp = ell + (size_t)4 * NN * CAP + mat * NN + row;

    int cnt = 0;
    for (int base = 0; base < NN / 4; base += 32) {
        float4 v = ar[base + lane];
        const int col0 = (base + lane) * 4;
        float e[4] = {v.x, v.y, v.z, v.w};
#pragma unroll
        for (int c = 0; c < 4; c++) {
            unsigned m = __ballot_sync(0xffffffffu, e[c] != 0.0f);
            if (e[c] != 0.0f) {
                int pos = cnt + __popc(m & ((1u << lane) - 1u));
                if (pos < CAP) idx[pos] = col0 + c;
            }
            cnt += __popc(m);
        }
    }
    if (lane == 0) *cntp = (cnt < CAP) ? cnt : CAP;
}

// ============================================================================
// Kernel 2: fused triple linear via 3xTF32 tensor-core MMA.
// Y[NN,768] = X[NN,K] @ [W0;W1;W2]^T + bias.  Wk is [256,K] row-major.
// Block tile 128(M) x 64(N), BK=8, 8 warps (4m x 2n), warp tile 32x32.
// fp32 split into tf32 hi+lo at smem-fill; 3 mma passes (hh, hl, lh).
// ============================================================================
__device__ __forceinline__ void f2tf2(float x, uint32_t& h, uint32_t& l) {
    asm("cvt.rna.tf32.f32 %0, %1;" : "=r"(h) : "f"(x));
    float r = x - __uint_as_float(h);
    asm("cvt.rna.tf32.f32 %0, %1;" : "=r"(l) : "f"(r));
}

__device__ __forceinline__ void mma_tf32(float* d, const uint32_t* a, const uint32_t* b) {
    asm volatile(
        "mma.sync.aligned.m16n8k8.row.col.f32.tf32.tf32.f32 "
        "{%0,%1,%2,%3}, {%4,%5,%6,%7}, {%8,%9}, {%0,%1,%2,%3};\n"
        : "+f"(d[0]), "+f"(d[1]), "+f"(d[2]), "+f"(d[3])
        : "r"(a[0]), "r"(a[1]), "r"(a[2]), "r"(a[3]), "r"(b[0]), "r"(b[1]));
}

#define APAD 12   // smem row stride (floats): 12 gives conflict-free frag LDS

template <int K>
__global__ __launch_bounds__(256, 2) void gemm3_tc(
    const float* __restrict__ X,
    const float* __restrict__ W0, const float* __restrict__ W1, const float* __restrict__ W2,
    const float* __restrict__ B0, const float* __restrict__ B1, const float* __restrict__ B2,
    float* __restrict__ Y)
{
    // [stage][hi/lo][row*APAD + k]
    __shared__ float sA[2][2][128 * APAD];
    __shared__ float sB[2][2][64 * APAD];

    const int m0 = blockIdx.x * 128;
    const int cb = blockIdx.y;                  // 0..11 -> 64-wide column block
    const int wsel = cb >> 2;
    const float* W  = (wsel == 0) ? W0 : (wsel == 1) ? W1 : W2;
    const float* Bv = (wsel == 0) ? B0 : (wsel == 1) ? B1 : B2;
    const int nW = (cb & 3) * 64;               // row offset inside W [256,K]

    const int tid  = threadIdx.x;
    const int lane = tid & 31, warp = tid >> 5;
    const int wm = warp >> 1, wn = warp & 1;    // 4 x 2 warps
    const int g  = lane >> 2, tig = lane & 3;

    // global load assignments
    const int arow = tid >> 1, alc = (tid & 1) * 4;          // A: 128 rows x 8k, float4
    const int brow = tid >> 2, blc = (tid & 3) * 2;          // B: 64 rows x 8k, float2
    const float* Ap = X + (size_t)(m0 + arow) * K + alc;
    const float* Bp = W + (size_t)(nW + brow) * K + blc;

    float acc[2][4][4];
#pragma unroll
    for (int mt = 0; mt < 2; mt++)
#pragma unroll
        for (int nt = 0; nt < 4; nt++)
#pragma unroll
            for (int i = 0; i < 4; i++) acc[mt][nt][i] = 0.f;

    constexpr int NT = K / 8;

    float4 av; float2 bv;

    // ---- preload tile 0 ----
    av = *(const float4*)(Ap);
    bv = *(const float2*)(Bp);
    {
        float ae[4] = {av.x, av.y, av.z, av.w};
        float4 h4, l4;
        f2tf2(ae[0], ((uint32_t*)&h4)[0], ((uint32_t*)&l4)[0]);
        f2tf2(ae[1], ((uint32_t*)&h4)[1], ((uint32_t*)&l4)[1]);
        f2tf2(ae[2], ((uint32_t*)&h4)[2], ((uint32_t*)&l4)[2]);
        f2tf2(ae[3], ((uint32_t*)&h4)[3], ((uint32_t*)&l4)[3]);
        *(float4*)&sA[0][0][arow * APAD + alc] = h4;
        *(float4*)&sA[0][1][arow * APAD + alc] = l4;
        float2 h2, l2;
        f2tf2(bv.x, ((uint32_t*)&h2)[0], ((uint32_t*)&l2)[0]);
        f2tf2(bv.y, ((uint32_t*)&h2)[1], ((uint32_t*)&l2)[1]);
        *(float2*)&sB[0][0][brow * APAD + blc] = h2;
        *(float2*)&sB[0][1][brow * APAD + blc] = l2;
    }
    __syncthreads();

#pragma unroll 1
    for (int t = 0; t < NT; t++) {
        const int cur = t & 1;
        if (t + 1 < NT) {
            av = *(const float4*)(Ap + (t + 1) * 8);
            bv = *(const float2*)(Bp + (t + 1) * 8);
        }

        // load fragments
        uint32_t ah[2][4], al[2][4], bh[4][2], bl[4][2];
        const float* AsH = sA[cur][0]; const float* AsL = sA[cur][1];
        const float* BsH = sB[cur][0]; const float* BsL = sB[cur][1];
#pragma unroll
        for (int mt = 0; mt < 2; mt++) {
            const int r0 = (wm * 32 + mt * 16 + g) * APAD;
            const int r8 = r0 + 8 * APAD;
            ah[mt][0] = __float_as_uint(AsH[r0 + tig]);
            ah[mt][1] = __float_as_uint(AsH[r8 + tig]);
            ah[mt][2] = __float_as_uint(AsH[r0 + tig + 4]);
            ah[mt][3] = __float_as_uint(AsH[r8 + tig + 4]);
            al[mt][0] = __float_as_uint(AsL[r0 + tig]);
            al[mt][1] = __float_as_uint(AsL[r8 + tig]);
            al[mt][2] = __float_as_uint(AsL[r0 + tig + 4]);
            al[mt][3] = __float_as_uint(AsL[r8 + tig + 4]);
        }
#pragma unroll
        for (int nt = 0; nt < 4; nt++) {
            const int r = (wn * 32 + nt * 8 + g) * APAD;
            bh[nt][0] = __float_as_uint(BsH[r + tig]);
            bh[nt][1] = __float_as_uint(BsH[r + tig + 4]);
            bl[nt][0] = __float_as_uint(BsL[r + tig]);
            bl[nt][1] = __float_as_uint(BsL[r + tig + 4]);
        }

#pragma unroll
        for (int mt = 0; mt < 2; mt++)
#pragma unroll
            for (int nt = 0; nt < 4; nt++) {
                mma_tf32(acc[mt][nt], ah[mt], bh[nt]);   // hi*hi
                mma_tf32(acc[mt][nt], ah[mt], bl[nt]);   // hi*lo
                mma_tf32(acc[mt][nt], al[mt], bh[nt]);   // lo*hi
            }

        if (t + 1 < NT) {
            const int nxt = cur ^ 1;
            float ae[4] = {av.x, av.y, av.z, av.w};
            float4 h4, l4;
            f2tf2(ae[0], ((uint32_t*)&h4)[0], ((uint32_t*)&l4)[0]);
            f2tf2(ae[1], ((uint32_t*)&h4)[1], ((uint32_t*)&l4)[1]);
            f2tf2(ae[2], ((uint32_t*)&h4)[2], ((uint32_t*)&l4)[2]);
            f2tf2(ae[3], ((uint32_t*)&h4)[3], ((uint32_t*)&l4)[3]);
            *(float4*)&sA[nxt][0][arow * APAD + alc] = h4;
            *(float4*)&sA[nxt][1][arow * APAD + alc] = l4;
            float2 h2, l2;
            f2tf2(bv.x, ((uint32_t*)&h2)[0], ((uint32_t*)&l2)[0]);
            f2tf2(bv.y, ((uint32_t*)&h2)[1], ((uint32_t*)&l2)[1]);
            *(float2*)&sB[nxt][0][brow * APAD + blc] = h2;
            *(float2*)&sB[nxt][1][brow * APAD + blc] = l2;
            __syncthreads();
        }
    }

    // ---- epilogue: bias + store ----
#pragma unroll
    for (int mt = 0; mt < 2; mt++) {
        const int r0 = m0 + wm * 32 + mt * 16 + g;
#pragma unroll
        for (int nt = 0; nt < 4; nt++) {
            const int cl = wn * 32 + nt * 8 + 2 * tig;   // 0..63 within block col tile
            const float b0 = Bv[nW + cl], b1 = Bv[nW + cl + 1];
            const int c = cb * 64 + cl;
            float2 v0 = {acc[mt][nt][0] + b0, acc[mt][nt][1] + b1};
            float2 v1 = {acc[mt][nt][2] + b0, acc[mt][nt][3] + b1};
            *(float2*)&Y[(size_t)r0 * TW + c]       = v0;
            *(float2*)&Y[(size_t)(r0 + 8) * TW + c] = v1;
        }
    }
}

// ============================================================================
// Kernel 3: combine. 4 rows per block, 64 threads per row, float4 gathers.
// ============================================================================
__global__ __launch_bounds__(256) void combine(
    const float* __restrict__ Tself, const float* __restrict__ Tother,
    const int* __restrict__ idx1, const int* __restrict__ cnt1,
    const int* __restrict__ idx2, const int* __restrict__ cnt2,
    float* __restrict__ outp, int do_norm)
{
    __shared__ int   sidx[4][2 * CAP];
    __shared__ float sred[8];
    const int tid = threadIdx.x;
    const int grp = tid >> 6, gt = tid & 63;
    const int row = blockIdx.x * 4 + grp;

    {   // load 256 indices (128 from each list) as int4
        const int4* p1 = (const int4*)(idx1 + (size_t)row * CAP);
        const int4* p2 = (const int4*)(idx2 + (size_t)row * CAP);
        int4 v = (gt < 32) ? p1[gt] : p2[gt - 32];
        ((int4*)sidx[grp])[gt] = v;
    }
    const int c1 = cnt1[row];
    const int c2 = cnt2[row];
    __syncthreads();

    const int* si = sidx[grp];
    float4 s0 = *(const float4*)&Tself[(size_t)row * TW + 4 * gt];
    float4 s1 = {0.f, 0.f, 0.f, 0.f}, s2 = {0.f, 0.f, 0.f, 0.f}, s3 = {0.f, 0.f, 0.f, 0.f};

    const float* b1 = Tother + 256 + 4 * gt;
    const float* b2 = Tother + 512 + 4 * gt;

    int j = 0;
    for (; j + 4 <= c1; j += 4) {
        float4 v0 = *(const float4*)(b1 + (size_t)si[j + 0] * TW);
        float4 v1 = *(const float4*)(b1 + (size_t)si[j + 1] * TW);
        float4 v2 = *(const float4*)(b1 + (size_t)si[j + 2] * TW);
        float4 v3 = *(const float4*)(b1 + (size_t)si[j + 3] * TW);
        s0.x += v0.x; s0.y += v0.y; s0.z += v0.z; s0.w += v0.w;
        s1.x += v1.x; s1.y += v1.y; s1.z += v1.z; s1.w += v1.w;
        s2.x += v2.x; s2.y += v2.y; s2.z += v2.z; s2.w += v2.w;
        s3.x += v3.x; s3.y += v3.y; s3.z += v3.z; s3.w += v3.w;
    }
    for (; j < c1; j++) {
        float4 v = *(const float4*)(b1 + (size_t)si[j] * TW);
        s0.x += v.x; s0.y += v.y; s0.z += v.z; s0.w += v.w;
    }
    for (j = 0; j + 4 <= c2; j += 4) {
        float4 v0 = *(const float4*)(b2 + (size_t)si[CAP + j + 0] * TW);
        float4 v1 = *(const float4*)(b2 + (size_t)si[CAP + j + 1] * TW);
        float4 v2 = *(const float4*)(b2 + (size_t)si[CAP + j + 2] * TW);
        float4 v3 = *(const float4*)(b2 + (size_t)si[CAP + j + 3] * TW);
        s0.x += v0.x; s0.y += v0.y; s0.z += v0.z; s0.w += v0.w;
        s1.x += v1.x; s1.y += v1.y; s1.z += v1.z; s1.w += v1.w;
        s2.x += v2.x; s2.y += v2.y; s2.z += v2.z; s2.w += v2.w;
        s3.x += v3.x; s3.y += v3.y; s3.z += v3.z; s3.w += v3.w;
    }
    for (; j < c2; j++) {
        float4 v = *(const float4*)(b2 + (size_t)si[CAP + j] * TW);
        s0.x += v.x; s0.y += v.y; s0.z += v.z; s0.w += v.w;
    }

    float4 a;
    a.x = (s0.x + s1.x) + (s2.x + s3.x);
    a.y = (s0.y + s1.y) + (s2.y + s3.y);
    a.z = (s0.z + s1.z) + (s2.z + s3.z);
    a.w = (s0.w + s1.w) + (s2.w + s3.w);
    a.x = (a.x > 0.f) ? a.x : 0.1f * a.x;
    a.y = (a.y > 0.f) ? a.y : 0.1f * a.y;
    a.z = (a.z > 0.f) ? a.z : 0.1f * a.z;
    a.w = (a.w > 0.f) ? a.w : 0.1f * a.w;

    if (do_norm) {
        float sq = a.x * a.x + a.y * a.y + a.z * a.z + a.w * a.w;
#pragma unroll
        for (int s = 16; s > 0; s >>= 1)
            sq += __shfl_xor_sync(0xffffffffu, sq, s);
        if ((gt & 31) == 0) sred[grp * 2 + (gt >> 5)] = sq;
        __syncthreads();
        const float tot = sred[grp * 2] + sred[grp * 2 + 1];
        const float inv = 1.0f / (sqrtf(tot) + 1e-9f);
        a.x *= inv; a.y *= inv; a.z *= inv; a.w *= inv;
    }
    *(float4*)&outp[(size_t)row * 256 + 4 * gt] = a;
}

// ============================================================================
// Host orchestration (graph-capturable: kernel launches only)
// ============================================================================
extern "C" void kernel_launch(void* const* d_in, const int* in_sizes, int n_in,
                              void* d_out, int out_size)
{
    const float* hp      = (const float*)d_in[0];
    const float* hq      = (const float*)d_in[1];
    const float* a_cons  = (const float*)d_in[2];
    const float* a_prod  = (const float*)d_in[3];
    const float* a_rcons = (const float*)d_in[4];
    const float* a_rprod = (const float*)d_in[5];
    const float* w[12];
    const float* b[12];
    for (int i = 0; i < 12; i++) {
        w[i] = (const float*)d_in[6 + 2 * i];
        b[i] = (const float*)d_in[7 + 2 * i];
    }
    float* out = (float*)d_out;

    float* scratch = nullptr;
    int*   ell     = nullptr;
    cudaGetSymbolAddress((void**)&scratch, g_scratch);
    cudaGetSymbolAddress((void**)&ell, g_ell);

    float* Tp  = scratch;
    float* Tq  = scratch + (size_t)NN * TW;
    float* hp1 = scratch + (size_t)2 * NN * TW;
    float* hq1 = hp1 + (size_t)NN * 256;

    int* idx[4];
    int* cnt[4];
    for (int m = 0; m < 4; m++) {
        idx[m] = ell + (size_t)m * NN * CAP;
        cnt[m] = ell + (size_t)4 * NN * CAP + (size_t)m * NN;
    }
    // mats: 0 = a_cons [P,Q], 1 = a_prod [Q,P], 2 = a_rev_cons [Q,P], 3 = a_rev_prod [P,Q]
    build_ell<<<dim3(NN / 8, 4), 256>>>(a_cons, a_prod, a_rcons, a_rprod, ell);

    // ---- layer 1 ----
    gemm3_tc<512><<<dim3(64, 12), 256>>>(hp, w[0], w[4], w[5], b[0], b[4], b[5], Tp);
    gemm3_tc<512><<<dim3(64, 12), 256>>>(hq, w[1], w[2], w[3], b[1], b[2], b[3], Tq);
    combine<<<NN / 4, 256>>>(Tp, Tq, idx[0], cnt[0], idx[3], cnt[3], hp1, 0);
    combine<<<NN / 4, 256>>>(Tq, Tp, idx[1], cnt[1], idx[2], cnt[2], hq1, 0);

    // ---- layer 2 ----
    gemm3_tc<256><<<dim3(64, 12), 256>>>(hp1, w[6], w[10], w[11], b[6], b[10], b[11], Tp);
    gemm3_tc<256><<<dim3(64, 12), 256>>>(hq1, w[7], w[8],  w[9],  b[7], b[8],  b[9],  Tq);
    combine<<<NN / 4, 256>>>(Tp, Tq, idx[0], cnt[0], idx[3], cnt[3], out, 1);
    combine<<<NN / 4, 256>>>(Tq, Tp, idx[1], cnt[1], idx[2], cnt[2], out + (size_t)NN * 256, 1);
}

// round 7
// speedup vs baseline: 1.4248x; 1.3246x over previous
#include <cuda_runtime.h>
#include <cstdint>
#include <cstddef>

// Problem constants (fixed by the dataset)
#define NN   8192      // NP == NQ
#define CAP  128       // ELL capacity per row
#define TW   768       // concatenated linear output width (3 x 256)

// -------- scratch (no allocations allowed) --------
__device__ float g_scratch[2 * NN * TW + 2 * NN * 256];
__device__ int   g_ell[4 * NN * CAP + 4 * NN];

// ============================================================================
// Kernel 1: dense adjacency -> ELL index lists (warp/row, float4 scan)
// ============================================================================
__global__ __launch_bounds__(256) void build_ell(
    const float* __restrict__ A0, const float* __restrict__ A1,
    const float* __restrict__ A2, const float* __restrict__ A3,
    int* __restrict__ ell)
{
    const int mat = blockIdx.y;
    const float* A = (mat == 0) ? A0 : (mat == 1) ? A1 : (mat == 2) ? A2 : A3;
    const int row  = blockIdx.x * 8 + (threadIdx.x >> 5);
    const int lane = threadIdx.x & 31;
    if (row >= NN) return;

    const float4* ar = (const float4*)(A + (size_t)row * NN);
    int* idx  = ell + (size_t)mat * NN * CAP + (size_t)row * CAP;
    int* cntp = ell + (size_t)4 * NN * CAP + mat * NN + row;

    int cnt = 0;
    for (int base = 0; base < NN / 4; base += 32) {
        float4 v = ar[base + lane];
        const int col0 = (base + lane) * 4;
        float e[4] = {v.x, v.y, v.z, v.w};
#pragma unroll
        for (int c = 0; c < 4; c++) {
            unsigned m = __ballot_sync(0xffffffffu, e[c] != 0.0f);
            if (e[c] != 0.0f) {
                int pos = cnt + __popc(m & ((1u << lane) - 1u));
                if (pos < CAP) idx[pos] = col0 + c;
            }
            cnt += __popc(m);
        }
    }
    if (lane == 0) *cntp = (cnt < CAP) ? cnt : CAP;
}

// ============================================================================
// Kernel 2: fused triple linear via bf16x3 (2-way split, 3-pass) m16n8k16 MMA.
// Y[NN,768] = X[NN,K] @ [W0;W1;W2]^T + bias.  Wk is [256,K] row-major.
// Block tile 128(M) x 64(N), BK=16, 8 warps (4m x 2n), warp tile 32x32.
// fp32 -> bf16 hi + bf16 lo at smem fill; passes hh, hl, lh (lo*lo ~2^-18).
// ============================================================================
__device__ __forceinline__ void bfsplit2(float x0, float x1, uint32_t& h, uint32_t& l) {
    // h = {bf16(x1) : bf16(x0)}, l = packed residuals
    asm("cvt.rn.bf16x2.f32 %0, %1, %2;" : "=r"(h) : "f"(x1), "f"(x0));
    float r0 = x0 - __uint_as_float(h << 16);
    float r1 = x1 - __uint_as_float(h & 0xffff0000u);
    asm("cvt.rn.bf16x2.f32 %0, %1, %2;" : "=r"(l) : "f"(r1), "f"(r0));
}

__device__ __forceinline__ void mma_bf16(float* d, const uint32_t* a, const uint32_t* b) {
    asm volatile(
        "mma.sync.aligned.m16n8k16.row.col.f32.bf16.bf16.f32 "
        "{%0,%1,%2,%3}, {%4,%5,%6,%7}, {%8,%9}, {%0,%1,%2,%3};\n"
        : "+f"(d[0]), "+f"(d[1]), "+f"(d[2]), "+f"(d[3])
        : "r"(a[0]), "r"(a[1]), "r"(a[2]), "r"(a[3]), "r"(b[0]), "r"(b[1]));
}

#define WSTRIDE 12   // smem row stride in 32-bit words (8 data + 4 pad): conflict-free

template <int K>
__global__ __launch_bounds__(256, 2) void gemm3_bf(
    const float* __restrict__ X,
    const float* __restrict__ W0, const float* __restrict__ W1, const float* __restrict__ W2,
    const float* __restrict__ B0, const float* __restrict__ B1, const float* __restrict__ B2,
    float* __restrict__ Y)
{
    // packed bf16x2 words: [stage][hi/lo][row * WSTRIDE + kword]
    __shared__ uint32_t sA[2][2][128 * WSTRIDE];
    __shared__ uint32_t sB[2][2][64 * WSTRIDE];

    const int m0 = blockIdx.x * 128;
    const int cb = blockIdx.y;                  // 0..11 -> 64-wide column block
    const int wsel = cb >> 2;
    const float* W  = (wsel == 0) ? W0 : (wsel == 1) ? W1 : W2;
    const float* Bv = (wsel == 0) ? B0 : (wsel == 1) ? B1 : B2;
    const int nW = (cb & 3) * 64;               // row offset inside W [256,K]

    const int tid  = threadIdx.x;
    const int lane = tid & 31, warp = tid >> 5;
    const int wm = warp >> 1, wn = warp & 1;    // 4 x 2 warps
    const int g  = lane >> 2, tig = lane & 3;

    // global load assignments (BK = 16 fp32)
    const int arow = tid >> 1, alc = (tid & 1) * 8;   // A: 128 rows x 16k, 2x float4/thread
    const int brow = tid >> 2, blc = (tid & 3) * 4;   // B: 64 rows x 16k, 1x float4/thread
    const float* Ap = X + (size_t)(m0 + arow) * K + alc;
    const float* Bp = W + (size_t)(nW + brow) * K + blc;

    float acc[2][4][4];
#pragma unroll
    for (int mt = 0; mt < 2; mt++)
#pragma unroll
        for (int nt = 0; nt < 4; nt++)
#pragma unroll
            for (int i = 0; i < 4; i++) acc[mt][nt][i] = 0.f;

    constexpr int NT = K / 16;

    float4 av0, av1, bv;

    // ---- fill helpers (inline) ----
    auto fillA = [&](int st, const float4& a0, const float4& a1) {
        uint4 h4, l4;
        bfsplit2(a0.x, a0.y, h4.x, l4.x);
        bfsplit2(a0.z, a0.w, h4.y, l4.y);
        bfsplit2(a1.x, a1.y, h4.z, l4.z);
        bfsplit2(a1.z, a1.w, h4.w, l4.w);
        *(uint4*)&sA[st][0][arow * WSTRIDE + alc / 2] = h4;
        *(uint4*)&sA[st][1][arow * WSTRIDE + alc / 2] = l4;
    };
    auto fillB = [&](int st, const float4& b0) {
        uint2 h2, l2;
        bfsplit2(b0.x, b0.y, h2.x, l2.x);
        bfsplit2(b0.z, b0.w, h2.y, l2.y);
        *(uint2*)&sB[st][0][brow * WSTRIDE + blc / 2] = h2;
        *(uint2*)&sB[st][1][brow * WSTRIDE + blc / 2] = l2;
    };

    // ---- preload tile 0 ----
    av0 = *(const float4*)(Ap);
    av1 = *(const float4*)(Ap + 4);
    bv  = *(const float4*)(Bp);
    fillA(0, av0, av1);
    fillB(0, bv);
    __syncthreads();

#pragma unroll 1
    for (int t = 0; t < NT; t++) {
        const int cur = t & 1;
        if (t + 1 < NT) {
            av0 = *(const float4*)(Ap + (t + 1) * 16);
            av1 = *(const float4*)(Ap + (t + 1) * 16 + 4);
            bv  = *(const float4*)(Bp + (t + 1) * 16);
        }

        // fragment loads: each 32-bit word = 2 bf16 k-values
        uint32_t ah[2][4], al[2][4], bh[4][2], bl[4][2];
        const uint32_t* AsH = sA[cur][0]; const uint32_t* AsL = sA[cur][1];
        const uint32_t* BsH = sB[cur][0]; const uint32_t* BsL = sB[cur][1];
#pragma unroll
        for (int mt = 0; mt < 2; mt++) {
            const int r0 = (wm * 32 + mt * 16 + g) * WSTRIDE;
            const int r8 = r0 + 8 * WSTRIDE;
            ah[mt][0] = AsH[r0 + tig];
            ah[mt][1] = AsH[r8 + tig];
            ah[mt][2] = AsH[r0 + tig + 4];
            ah[mt][3] = AsH[r8 + tig + 4];
            al[mt][0] = AsL[r0 + tig];
            al[mt][1] = AsL[r8 + tig];
            al[mt][2] = AsL[r0 + tig + 4];
            al[mt][3] = AsL[r8 + tig + 4];
        }
#pragma unroll
        for (int nt = 0; nt < 4; nt++) {
            const int r = (wn * 32 + nt * 8 + g) * WSTRIDE;
            bh[nt][0] = BsH[r + tig];
            bh[nt][1] = BsH[r + tig + 4];
            bl[nt][0] = BsL[r + tig];
            bl[nt][1] = BsL[r + tig + 4];
        }

#pragma unroll
        for (int mt = 0; mt < 2; mt++)
#pragma unroll
            for (int nt = 0; nt < 4; nt++) {
                mma_bf16(acc[mt][nt], ah[mt], bh[nt]);   // hi*hi
                mma_bf16(acc[mt][nt], ah[mt], bl[nt]);   // hi*lo
                mma_bf16(acc[mt][nt], al[mt], bh[nt]);   // lo*hi
            }

        if (t + 1 < NT) {
            const int nxt = cur ^ 1;
            fillA(nxt, av0, av1);
            fillB(nxt, bv);
            __syncthreads();
        }
    }

    // ---- epilogue: bias + store (layout identical to m16n8k8 case) ----
#pragma unroll
    for (int mt = 0; mt < 2; mt++) {
        const int r0 = m0 + wm * 32 + mt * 16 + g;
#pragma unroll
        for (int nt = 0; nt < 4; nt++) {
            const int cl = wn * 32 + nt * 8 + 2 * tig;   // 0..63 within block col tile
            const float b0 = Bv[nW + cl], b1 = Bv[nW + cl + 1];
            const int c = cb * 64 + cl;
            float2 v0 = {acc[mt][nt][0] + b0, acc[mt][nt][1] + b1};
            float2 v1 = {acc[mt][nt][2] + b0, acc[mt][nt][3] + b1};
            *(float2*)&Y[(size_t)r0 * TW + c]       = v0;
            *(float2*)&Y[(size_t)(r0 + 8) * TW + c] = v1;
        }
    }
}

// ============================================================================
// Kernel 3: combine. 4 rows per block, 64 threads per row, float4 gathers.
// ============================================================================
__global__ __launch_bounds__(256) void combine(
    const float* __restrict__ Tself, const float* __restrict__ Tother,
    const int* __restrict__ idx1, const int* __restrict__ cnt1,
    const int* __restrict__ idx2, const int* __restrict__ cnt2,
    float* __restrict__ outp, int do_norm)
{
    __shared__ int   sidx[4][2 * CAP];
    __shared__ float sred[8];
    const int tid = threadIdx.x;
    const int grp = tid >> 6, gt = tid & 63;
    const int row = blockIdx.x * 4 + grp;

    {   // load 256 indices (128 from each list) as int4
        const int4* p1 = (const int4*)(idx1 + (size_t)row * CAP);
        const int4* p2 = (const int4*)(idx2 + (size_t)row * CAP);
        int4 v = (gt < 32) ? p1[gt] : p2[gt - 32];
        ((int4*)sidx[grp])[gt] = v;
    }
    const int c1 = cnt1[row];
    const int c2 = cnt2[row];
    __syncthreads();

    const int* si = sidx[grp];
    float4 s0 = *(const float4*)&Tself[(size_t)row * TW + 4 * gt];
    float4 s1 = {0.f, 0.f, 0.f, 0.f}, s2 = {0.f, 0.f, 0.f, 0.f}, s3 = {0.f, 0.f, 0.f, 0.f};

    const float* b1 = Tother + 256 + 4 * gt;
    const float* b2 = Tother + 512 + 4 * gt;

    int j = 0;
    for (; j + 4 <= c1; j += 4) {
        float4 v0 = *(const float4*)(b1 + (size_t)si[j + 0] * TW);
        float4 v1 = *(const float4*)(b1 + (size_t)si[j + 1] * TW);
        float4 v2 = *(const float4*)(b1 + (size_t)si[j + 2] * TW);
        float4 v3 = *(const float4*)(b1 + (size_t)si[j + 3] * TW);
        s0.x += v0.x; s0.y += v0.y; s0.z += v0.z; s0.w += v0.w;
        s1.x += v1.x; s1.y += v1.y; s1.z += v1.z; s1.w += v1.w;
        s2.x += v2.x; s2.y += v2.y; s2.z += v2.z; s2.w += v2.w;
        s3.x += v3.x; s3.y += v3.y; s3.z += v3.z; s3.w += v3.w;
    }
    for (; j < c1; j++) {
        float4 v = *(const float4*)(b1 + (size_t)si[j] * TW);
        s0.x += v.x; s0.y += v.y; s0.z += v.z; s0.w += v.w;
    }
    for (j = 0; j + 4 <= c2; j += 4) {
        float4 v0 = *(const float4*)(b2 + (size_t)si[CAP + j + 0] * TW);
        float4 v1 = *(const float4*)(b2 + (size_t)si[CAP + j + 1] * TW);
        float4 v2 = *(const float4*)(b2 + (size_t)si[CAP + j + 2] * TW);
        float4 v3 = *(const float4*)(b2 + (size_t)si[CAP + j + 3] * TW);
        s0.x += v0.x; s0.y += v0.y; s0.z += v0.z; s0.w += v0.w;
        s1.x += v1.x; s1.y += v1.y; s1.z += v1.z; s1.w += v1.w;
        s2.x += v2.x; s2.y += v2.y; s2.z += v2.z; s2.w += v2.w;
        s3.x += v3.x; s3.y += v3.y; s3.z += v3.z; s3.w += v3.w;
    }
    for (; j < c2; j++) {
        float4 v = *(const float4*)(b2 + (size_t)si[CAP + j] * TW);
        s0.x += v.x; s0.y += v.y; s0.z += v.z; s0.w += v.w;
    }

    float4 a;
    a.x = (s0.x + s1.x) + (s2.x + s3.x);
    a.y = (s0.y + s1.y) + (s2.y + s3.y);
    a.z = (s0.z + s1.z) + (s2.z + s3.z);
    a.w = (s0.w + s1.w) + (s2.w + s3.w);
    a.x = (a.x > 0.f) ? a.x : 0.1f * a.x;
    a.y = (a.y > 0.f) ? a.y : 0.1f * a.y;
    a.z = (a.z > 0.f) ? a.z : 0.1f * a.z;
    a.w = (a.w > 0.f) ? a.w : 0.1f * a.w;

    if (do_norm) {
        float sq = a.x * a.x + a.y * a.y + a.z * a.z + a.w * a.w;
#pragma unroll
        for (int s = 16; s > 0; s >>= 1)
            sq += __shfl_xor_sync(0xffffffffu, sq, s);
        if ((gt & 31) == 0) sred[grp * 2 + (gt >> 5)] = sq;
        __syncthreads();
        const float tot = sred[grp * 2] + sred[grp * 2 + 1];
        const float inv = 1.0f / (sqrtf(tot) + 1e-9f);
        a.x *= inv; a.y *= inv; a.z *= inv; a.w *= inv;
    }
    *(float4*)&outp[(size_t)row * 256 + 4 * gt] = a;
}

// ============================================================================
// Host orchestration (graph-capturable: kernel launches only)
// ============================================================================
extern "C" void kernel_launch(void* const* d_in, const int* in_sizes, int n_in,
                              void* d_out, int out_size)
{
    const float* hp      = (const float*)d_in[0];
    const float* hq      = (const float*)d_in[1];
    const float* a_cons  = (const float*)d_in[2];
    const float* a_prod  = (const float*)d_in[3];
    const float* a_rcons = (const float*)d_in[4];
    const float* a_rprod = (const float*)d_in[5];
    const float* w[12];
    const float* b[12];
    for (int i = 0; i < 12; i++) {
        w[i] = (const float*)d_in[6 + 2 * i];
        b[i] = (const float*)d_in[7 + 2 * i];
    }
    float* out = (float*)d_out;

    float* scratch = nullptr;
    int*   ell     = nullptr;
    cudaGetSymbolAddress((void**)&scratch, g_scratch);
    cudaGetSymbolAddress((void**)&ell, g_ell);

    float* Tp  = scratch;
    float* Tq  = scratch + (size_t)NN * TW;
    float* hp1 = scratch + (size_t)2 * NN * TW;
    float* hq1 = hp1 + (size_t)NN * 256;

    int* idx[4];
    int* cnt[4];
    for (int m = 0; m < 4; m++) {
        idx[m] = ell + (size_t)m * NN * CAP;
        cnt[m] = ell + (size_t)4 * NN * CAP + (size_t)m * NN;
    }
    // mats: 0 = a_cons [P,Q], 1 = a_prod [Q,P], 2 = a_rev_cons [Q,P], 3 = a_rev_prod [P,Q]
    build_ell<<<dim3(NN / 8, 4), 256>>>(a_cons, a_prod, a_rcons, a_rprod, ell);

    // ---- layer 1 ----
    gemm3_bf<512><<<dim3(64, 12), 256>>>(hp, w[0], w[4], w[5], b[0], b[4], b[5], Tp);
    gemm3_bf<512><<<dim3(64, 12), 256>>>(hq, w[1], w[2], w[3], b[1], b[2], b[3], Tq);
    combine<<<NN / 4, 256>>>(Tp, Tq, idx[0], cnt[0], idx[3], cnt[3], hp1, 0);
    combine<<<NN / 4, 256>>>(Tq, Tp, idx[1], cnt[1], idx[2], cnt[2], hq1, 0);

    // ---- layer 2 ----
    gemm3_bf<256><<<dim3(64, 12), 256>>>(hp1, w[6], w[10], w[11], b[6], b[10], b[11], Tp);
    gemm3_bf<256><<<dim3(64, 12), 256>>>(hq1, w[7], w[8],  w[9],  b[7], b[8],  b[9],  Tq);
    combine<<<NN / 4, 256>>>(Tp, Tq, idx[0], cnt[0], idx[3], cnt[3], out, 1);
    combine<<<NN / 4, 256>>>(Tq, Tp, idx[1], cnt[1], idx[2], cnt[2], out + (size_t)NN * 256, 1);
}